// round 1
// baseline (speedup 1.0000x reference)
#include <cuda_runtime.h>

// Problem constants
#define NB   4
#define LSEQ 2048
#define HH   8
#define DKH  64
#define DMOD 512
#define MTOT (NB * LSEQ)   // 8192

// Scratch (static device globals; no runtime allocation)
__device__ float g_q[(size_t)NB * HH * LSEQ * DKH];     // [b,h,l,d]
__device__ float g_k[(size_t)NB * HH * LSEQ * DKH];
__device__ float g_v[(size_t)NB * HH * LSEQ * DKH];
__device__ float g_attn[(size_t)MTOT * DMOD];           // [b*l, h*d] concatenated heads

// ----------------------------------------------------------------------------
// GEMM: out[M,N] = X[M,512] @ W[N,512]^T + bias   (M=8192, N=512, K=512)
// BM=BN=128, BK=16, 256 threads, 8x8 microtile.
// HEAD=true writes into [b,h,l,d] head layout instead of [m,n].
// ----------------------------------------------------------------------------
template <bool HEAD>
__global__ __launch_bounds__(256, 2)
void gemm512(const float* __restrict__ X, const float* __restrict__ W,
             const float* __restrict__ bias, float* __restrict__ out)
{
    __shared__ float As[16 * 128];   // k-major: As[k][m]
    __shared__ float Bs[16 * 128];   // k-major: Bs[k][n]

    const int tid = threadIdx.x;
    const int tx = tid & 15;
    const int ty = tid >> 4;
    const int m0 = blockIdx.y * 128;
    const int n0 = blockIdx.x * 128;

    const int lrow = tid >> 1;         // 0..127
    const int kh   = (tid & 1) * 8;    // 0 or 8

    float acc[8][8];
#pragma unroll
    for (int i = 0; i < 8; i++)
#pragma unroll
        for (int j = 0; j < 8; j++) acc[i][j] = 0.0f;

    for (int k0 = 0; k0 < 512; k0 += 16) {
        // Issue global loads early
        const float4* xa = (const float4*)(X + (size_t)(m0 + lrow) * 512 + k0 + kh);
        float4 a0 = xa[0];
        float4 a1 = xa[1];
        const float4* wb = (const float4*)(W + (size_t)(n0 + lrow) * 512 + k0 + kh);
        float4 b0 = wb[0];
        float4 b1 = wb[1];

        __syncthreads();   // previous tile fully consumed
        As[(kh + 0) * 128 + lrow] = a0.x;
        As[(kh + 1) * 128 + lrow] = a0.y;
        As[(kh + 2) * 128 + lrow] = a0.z;
        As[(kh + 3) * 128 + lrow] = a0.w;
        As[(kh + 4) * 128 + lrow] = a1.x;
        As[(kh + 5) * 128 + lrow] = a1.y;
        As[(kh + 6) * 128 + lrow] = a1.z;
        As[(kh + 7) * 128 + lrow] = a1.w;
        Bs[(kh + 0) * 128 + lrow] = b0.x;
        Bs[(kh + 1) * 128 + lrow] = b0.y;
        Bs[(kh + 2) * 128 + lrow] = b0.z;
        Bs[(kh + 3) * 128 + lrow] = b0.w;
        Bs[(kh + 4) * 128 + lrow] = b1.x;
        Bs[(kh + 5) * 128 + lrow] = b1.y;
        Bs[(kh + 6) * 128 + lrow] = b1.z;
        Bs[(kh + 7) * 128 + lrow] = b1.w;
        __syncthreads();

#pragma unroll
        for (int kk = 0; kk < 16; kk++) {
            float4 av0 = *(const float4*)&As[kk * 128 + ty * 8];
            float4 av1 = *(const float4*)&As[kk * 128 + ty * 8 + 4];
            float4 bv0 = *(const float4*)&Bs[kk * 128 + tx * 8];
            float4 bv1 = *(const float4*)&Bs[kk * 128 + tx * 8 + 4];
            float a[8] = {av0.x, av0.y, av0.z, av0.w, av1.x, av1.y, av1.z, av1.w};
            float b[8] = {bv0.x, bv0.y, bv0.z, bv0.w, bv1.x, bv1.y, bv1.z, bv1.w};
#pragma unroll
            for (int i = 0; i < 8; i++)
#pragma unroll
                for (int j = 0; j < 8; j++)
                    acc[i][j] = fmaf(a[i], b[j], acc[i][j]);
        }
    }

    // Epilogue: bias + store
#pragma unroll
    for (int i = 0; i < 8; i++) {
        const int m = m0 + ty * 8 + i;
#pragma unroll
        for (int j = 0; j < 8; j++) {
            const int c = n0 + tx * 8 + j;
            const float v = acc[i][j] + bias[c];
            if (HEAD) {
                const int bb = m >> 11;            // / LSEQ
                const int l  = m & (LSEQ - 1);
                const int h  = c >> 6;             // / DKH
                const int d  = c & 63;
                out[((((size_t)bb * HH + h) * LSEQ) + l) * DKH + d] = v;
            } else {
                out[(size_t)m * DMOD + c] = v;
            }
        }
    }
}

// ----------------------------------------------------------------------------
// Flash attention: BQ=128 query rows, BK=64 keys per step, d_k=64.
// 256 threads (16x16); each thread owns 8 query rows x 4 cols.
// smem tiles are k-major (transposed) so inner products read float4s.
// ----------------------------------------------------------------------------
#define ATTN_SMEM_FLOATS (64 * 128 + 64 * 64 + 64 * 64 + 64 * 128)  // 24576

__global__ __launch_bounds__(256, 2)
void attn512(const float* __restrict__ Q, const float* __restrict__ K,
             const float* __restrict__ V, const int* __restrict__ mask,
             float* __restrict__ out)
{
    extern __shared__ float sm[];
    float* Qt = sm;                   // [d=64][r=128]
    float* Kt = Qt + 64 * 128;        // [d=64][c=64]
    float* Vs = Kt + 64 * 64;         // [k=64][d=64] natural
    float* Pt = Vs + 64 * 64;         // [k=64][r=128]

    const int tid = threadIdx.x;
    const int tx = tid & 15;
    const int ty = tid >> 4;
    const int q0 = blockIdx.x * 128;
    const int bh = blockIdx.y;        // 0..31
    const int b  = bh >> 3;
    const int h  = bh & 7;

    // Load Q tile transposed, pre-scaled by 1/sqrt(d_k)
    const float* qbase = Q + ((size_t)bh * LSEQ + q0) * DKH;
#pragma unroll
    for (int i = 0; i < 8; i++) {
        const int e = tid + i * 256;
        const int row = e >> 4;
        const int c4  = (e & 15) * 4;
        float4 val = *(const float4*)(qbase + row * 64 + c4);
        Qt[(c4 + 0) * 128 + row] = val.x * 0.125f;
        Qt[(c4 + 1) * 128 + row] = val.y * 0.125f;
        Qt[(c4 + 2) * 128 + row] = val.z * 0.125f;
        Qt[(c4 + 3) * 128 + row] = val.w * 0.125f;
    }

    float m_i[8], l_i[8], O[8][4];
#pragma unroll
    for (int i = 0; i < 8; i++) {
        m_i[i] = -1e30f;
        l_i[i] = 0.0f;
#pragma unroll
        for (int j = 0; j < 4; j++) O[i][j] = 0.0f;
    }

    const float* kbh = K + (size_t)bh * LSEQ * DKH;
    const float* vbh = V + (size_t)bh * LSEQ * DKH;
    const int* mrow = mask + b * LSEQ;

    for (int kt = 0; kt < LSEQ; kt += 64) {
        __syncthreads();   // previous Pt/Kt/Vs fully consumed
        // Load K tile transposed + V tile natural
#pragma unroll
        for (int i = 0; i < 4; i++) {
            const int e = tid + i * 256;
            const int row = e >> 4;
            const int c4  = (e & 15) * 4;
            float4 kv = *(const float4*)(kbh + (size_t)(kt + row) * 64 + c4);
            Kt[(c4 + 0) * 64 + row] = kv.x;
            Kt[(c4 + 1) * 64 + row] = kv.y;
            Kt[(c4 + 2) * 64 + row] = kv.z;
            Kt[(c4 + 3) * 64 + row] = kv.w;
            float4 vv = *(const float4*)(vbh + (size_t)(kt + row) * 64 + c4);
            *(float4*)&Vs[row * 64 + c4] = vv;
        }
        __syncthreads();

        // S = (Q/8) @ K^T
        float s[8][4];
#pragma unroll
        for (int i = 0; i < 8; i++)
#pragma unroll
            for (int j = 0; j < 4; j++) s[i][j] = 0.0f;

#pragma unroll 4
        for (int d = 0; d < 64; d++) {
            float4 qv0 = *(const float4*)&Qt[d * 128 + ty * 8];
            float4 qv1 = *(const float4*)&Qt[d * 128 + ty * 8 + 4];
            float4 kv  = *(const float4*)&Kt[d * 64 + tx * 4];
            float qa[8] = {qv0.x, qv0.y, qv0.z, qv0.w, qv1.x, qv1.y, qv1.z, qv1.w};
            float ka[4] = {kv.x, kv.y, kv.z, kv.w};
#pragma unroll
            for (int i = 0; i < 8; i++)
#pragma unroll
                for (int j = 0; j < 4; j++)
                    s[i][j] = fmaf(qa[i], ka[j], s[i][j]);
        }

        // mask (N,1,L) broadcast over query rows
        int mk[4];
#pragma unroll
        for (int j = 0; j < 4; j++) mk[j] = mrow[kt + tx * 4 + j];
#pragma unroll
        for (int i = 0; i < 8; i++)
#pragma unroll
            for (int j = 0; j < 4; j++)
                if (mk[j] == 0) s[i][j] = -1e9f;

        // Online softmax update (16-lane row groups; shfl_xor stays in group)
#pragma unroll
        for (int i = 0; i < 8; i++) {
            float mx = fmaxf(fmaxf(s[i][0], s[i][1]), fmaxf(s[i][2], s[i][3]));
#pragma unroll
            for (int off = 1; off < 16; off <<= 1)
                mx = fmaxf(mx, __shfl_xor_sync(0xffffffffu, mx, off));
            const float mn = fmaxf(m_i[i], mx);
            const float corr = __expf(m_i[i] - mn);
            float rs = 0.0f;
#pragma unroll
            for (int j = 0; j < 4; j++) {
                s[i][j] = __expf(s[i][j] - mn);
                rs += s[i][j];
            }
#pragma unroll
            for (int off = 1; off < 16; off <<= 1)
                rs += __shfl_xor_sync(0xffffffffu, rs, off);
            l_i[i] = l_i[i] * corr + rs;
            m_i[i] = mn;
#pragma unroll
            for (int j = 0; j < 4; j++) O[i][j] *= corr;
        }

        // Write P transposed: Pt[k][r]
#pragma unroll
        for (int j = 0; j < 4; j++) {
            const int c = tx * 4 + j;
#pragma unroll
            for (int i = 0; i < 8; i++)
                Pt[c * 128 + ty * 8 + i] = s[i][j];
        }
        __syncthreads();

        // O += P @ V
#pragma unroll 4
        for (int kk = 0; kk < 64; kk++) {
            float4 pv0 = *(const float4*)&Pt[kk * 128 + ty * 8];
            float4 pv1 = *(const float4*)&Pt[kk * 128 + ty * 8 + 4];
            float4 vv  = *(const float4*)&Vs[kk * 64 + tx * 4];
            float pa[8] = {pv0.x, pv0.y, pv0.z, pv0.w, pv1.x, pv1.y, pv1.z, pv1.w};
            float va[4] = {vv.x, vv.y, vv.z, vv.w};
#pragma unroll
            for (int i = 0; i < 8; i++)
#pragma unroll
                for (int j = 0; j < 4; j++)
                    O[i][j] = fmaf(pa[i], va[j], O[i][j]);
        }
    }

    // Normalize and write concatenated-head layout [b*l, h*64+d]
#pragma unroll
    for (int i = 0; i < 8; i++) {
        const float inv = 1.0f / l_i[i];
        const int row = q0 + ty * 8 + i;
#pragma unroll
        for (int j = 0; j < 4; j++)
            out[((size_t)b * LSEQ + row) * DMOD + h * DKH + tx * 4 + j] = O[i][j] * inv;
    }
}

// ----------------------------------------------------------------------------
extern "C" void kernel_launch(void* const* d_in, const int* in_sizes, int n_in,
                              void* d_out, int out_size)
{
    const float* query = (const float*)d_in[0];
    const float* key   = (const float*)d_in[1];
    const float* value = (const float*)d_in[2];
    const int*   mask  = (const int*)  d_in[3];
    const float* Wq = (const float*)d_in[4];
    const float* bq = (const float*)d_in[5];
    const float* Wk = (const float*)d_in[6];
    const float* bk = (const float*)d_in[7];
    const float* Wv = (const float*)d_in[8];
    const float* bv = (const float*)d_in[9];
    const float* Wo = (const float*)d_in[10];
    const float* bo = (const float*)d_in[11];
    float* out = (float*)d_out;

    float *qb, *kb, *vb, *ab;
    cudaGetSymbolAddress((void**)&qb, g_q);
    cudaGetSymbolAddress((void**)&kb, g_k);
    cudaGetSymbolAddress((void**)&vb, g_v);
    cudaGetSymbolAddress((void**)&ab, g_attn);

    const int attn_smem = ATTN_SMEM_FLOATS * (int)sizeof(float);  // 96 KB
    cudaFuncSetAttribute(attn512, cudaFuncAttributeMaxDynamicSharedMemorySize, attn_smem);

    dim3 blk(256);
    dim3 ggrid(DMOD / 128, MTOT / 128);   // (4, 64)

    gemm512<true><<<ggrid, blk>>>(query, Wq, bq, qb);
    gemm512<true><<<ggrid, blk>>>(key,   Wk, bk, kb);
    gemm512<true><<<ggrid, blk>>>(value, Wv, bv, vb);

    attn512<<<dim3(LSEQ / 128, NB * HH), blk, attn_smem>>>(qb, kb, vb, mask, ab);

    gemm512<false><<<ggrid, blk>>>(ab, Wo, bo, out);
}

// round 4
// speedup vs baseline: 1.0012x; 1.0012x over previous
#include <cuda_runtime.h>

// Problem constants
#define NB   4
#define LSEQ 2048
#define HH   8
#define DKH  64
#define DMOD 512
#define MTOT (NB * LSEQ)   // 8192

// Scratch (static device globals; no runtime allocation)
__device__ float g_q[(size_t)NB * HH * LSEQ * DKH];     // [b,h,l,d]
__device__ float g_k[(size_t)NB * HH * LSEQ * DKH];
__device__ float g_v[(size_t)NB * HH * LSEQ * DKH];
__device__ float g_attn[(size_t)MTOT * DMOD];           // [b*l, h*d] concatenated heads

// ----------------------------------------------------------------------------
// GEMM: out[M,N] = X[M,512] @ W[N,512]^T + bias   (M=8192, N=512, K=512)
// BM=BN=128, BK=16, 256 threads, 8x8 microtile.
// HEAD=true writes into [b,h,l,d] head layout instead of [m,n].
// ----------------------------------------------------------------------------
template <bool HEAD>
__global__ __launch_bounds__(256, 2)
void gemm512(const float* __restrict__ X, const float* __restrict__ W,
             const float* __restrict__ bias, float* __restrict__ out)
{
    __shared__ float As[16 * 128];   // k-major: As[k][m]
    __shared__ float Bs[16 * 128];   // k-major: Bs[k][n]

    const int tid = threadIdx.x;
    const int tx = tid & 15;
    const int ty = tid >> 4;
    const int m0 = blockIdx.y * 128;
    const int n0 = blockIdx.x * 128;

    const int lrow = tid >> 1;         // 0..127
    const int kh   = (tid & 1) * 8;    // 0 or 8

    float acc[8][8];
#pragma unroll
    for (int i = 0; i < 8; i++)
#pragma unroll
        for (int j = 0; j < 8; j++) acc[i][j] = 0.0f;

    for (int k0 = 0; k0 < 512; k0 += 16) {
        // Issue global loads early
        const float4* xa = (const float4*)(X + (size_t)(m0 + lrow) * 512 + k0 + kh);
        float4 a0 = xa[0];
        float4 a1 = xa[1];
        const float4* wb = (const float4*)(W + (size_t)(n0 + lrow) * 512 + k0 + kh);
        float4 b0 = wb[0];
        float4 b1 = wb[1];

        __syncthreads();   // previous tile fully consumed
        As[(kh + 0) * 128 + lrow] = a0.x;
        As[(kh + 1) * 128 + lrow] = a0.y;
        As[(kh + 2) * 128 + lrow] = a0.z;
        As[(kh + 3) * 128 + lrow] = a0.w;
        As[(kh + 4) * 128 + lrow] = a1.x;
        As[(kh + 5) * 128 + lrow] = a1.y;
        As[(kh + 6) * 128 + lrow] = a1.z;
        As[(kh + 7) * 128 + lrow] = a1.w;
        Bs[(kh + 0) * 128 + lrow] = b0.x;
        Bs[(kh + 1) * 128 + lrow] = b0.y;
        Bs[(kh + 2) * 128 + lrow] = b0.z;
        Bs[(kh + 3) * 128 + lrow] = b0.w;
        Bs[(kh + 4) * 128 + lrow] = b1.x;
        Bs[(kh + 5) * 128 + lrow] = b1.y;
        Bs[(kh + 6) * 128 + lrow] = b1.z;
        Bs[(kh + 7) * 128 + lrow] = b1.w;
        __syncthreads();

#pragma unroll
        for (int kk = 0; kk < 16; kk++) {
            float4 av0 = *(const float4*)&As[kk * 128 + ty * 8];
            float4 av1 = *(const float4*)&As[kk * 128 + ty * 8 + 4];
            float4 bv0 = *(const float4*)&Bs[kk * 128 + tx * 8];
            float4 bv1 = *(const float4*)&Bs[kk * 128 + tx * 8 + 4];
            float a[8] = {av0.x, av0.y, av0.z, av0.w, av1.x, av1.y, av1.z, av1.w};
            float b[8] = {bv0.x, bv0.y, bv0.z, bv0.w, bv1.x, bv1.y, bv1.z, bv1.w};
#pragma unroll
            for (int i = 0; i < 8; i++)
#pragma unroll
                for (int j = 0; j < 8; j++)
                    acc[i][j] = fmaf(a[i], b[j], acc[i][j]);
        }
    }

    // Epilogue: bias + store
#pragma unroll
    for (int i = 0; i < 8; i++) {
        const int m = m0 + ty * 8 + i;
#pragma unroll
        for (int j = 0; j < 8; j++) {
            const int c = n0 + tx * 8 + j;
            const float v = acc[i][j] + bias[c];
            if (HEAD) {
                const int bb = m >> 11;            // / LSEQ
                const int l  = m & (LSEQ - 1);
                const int h  = c >> 6;             // / DKH
                const int d  = c & 63;
                out[((((size_t)bb * HH + h) * LSEQ) + l) * DKH + d] = v;
            } else {
                out[(size_t)m * DMOD + c] = v;
            }
        }
    }
}

// ----------------------------------------------------------------------------
// Flash attention: BQ=128 query rows, BK=64 keys per step, d_k=64.
// 256 threads (16x16); each thread owns 8 query rows x 4 cols.
// smem tiles are k-major (transposed) so inner products read float4s.
// ----------------------------------------------------------------------------
#define ATTN_SMEM_FLOATS (64 * 128 + 64 * 64 + 64 * 64 + 64 * 128)  // 24576

__global__ __launch_bounds__(256, 2)
void attn512(const float* __restrict__ Q, const float* __restrict__ K,
             const float* __restrict__ V, const int* __restrict__ mask,
             float* __restrict__ out)
{
    extern __shared__ float sm[];
    float* Qt = sm;                   // [d=64][r=128]
    float* Kt = Qt + 64 * 128;        // [d=64][c=64]
    float* Vs = Kt + 64 * 64;         // [k=64][d=64] natural
    float* Pt = Vs + 64 * 64;         // [k=64][r=128]

    const int tid = threadIdx.x;
    const int tx = tid & 15;
    const int ty = tid >> 4;
    const int q0 = blockIdx.x * 128;
    const int bh = blockIdx.y;        // 0..31
    const int b  = bh >> 3;
    const int h  = bh & 7;

    // Load Q tile transposed, pre-scaled by 1/sqrt(d_k)
    const float* qbase = Q + ((size_t)bh * LSEQ + q0) * DKH;
#pragma unroll
    for (int i = 0; i < 8; i++) {
        const int e = tid + i * 256;
        const int row = e >> 4;
        const int c4  = (e & 15) * 4;
        float4 val = *(const float4*)(qbase + row * 64 + c4);
        Qt[(c4 + 0) * 128 + row] = val.x * 0.125f;
        Qt[(c4 + 1) * 128 + row] = val.y * 0.125f;
        Qt[(c4 + 2) * 128 + row] = val.z * 0.125f;
        Qt[(c4 + 3) * 128 + row] = val.w * 0.125f;
    }

    float m_i[8], l_i[8], O[8][4];
#pragma unroll
    for (int i = 0; i < 8; i++) {
        m_i[i] = -1e30f;
        l_i[i] = 0.0f;
#pragma unroll
        for (int j = 0; j < 4; j++) O[i][j] = 0.0f;
    }

    const float* kbh = K + (size_t)bh * LSEQ * DKH;
    const float* vbh = V + (size_t)bh * LSEQ * DKH;
    const int* mrow = mask + b * LSEQ;

    for (int kt = 0; kt < LSEQ; kt += 64) {
        __syncthreads();   // previous Pt/Kt/Vs fully consumed
        // Load K tile transposed + V tile natural
#pragma unroll
        for (int i = 0; i < 4; i++) {
            const int e = tid + i * 256;
            const int row = e >> 4;
            const int c4  = (e & 15) * 4;
            float4 kv = *(const float4*)(kbh + (size_t)(kt + row) * 64 + c4);
            Kt[(c4 + 0) * 64 + row] = kv.x;
            Kt[(c4 + 1) * 64 + row] = kv.y;
            Kt[(c4 + 2) * 64 + row] = kv.z;
            Kt[(c4 + 3) * 64 + row] = kv.w;
            float4 vv = *(const float4*)(vbh + (size_t)(kt + row) * 64 + c4);
            *(float4*)&Vs[row * 64 + c4] = vv;
        }
        __syncthreads();

        // S = (Q/8) @ K^T
        float s[8][4];
#pragma unroll
        for (int i = 0; i < 8; i++)
#pragma unroll
            for (int j = 0; j < 4; j++) s[i][j] = 0.0f;

#pragma unroll 4
        for (int d = 0; d < 64; d++) {
            float4 qv0 = *(const float4*)&Qt[d * 128 + ty * 8];
            float4 qv1 = *(const float4*)&Qt[d * 128 + ty * 8 + 4];
            float4 kv  = *(const float4*)&Kt[d * 64 + tx * 4];
            float qa[8] = {qv0.x, qv0.y, qv0.z, qv0.w, qv1.x, qv1.y, qv1.z, qv1.w};
            float ka[4] = {kv.x, kv.y, kv.z, kv.w};
#pragma unroll
            for (int i = 0; i < 8; i++)
#pragma unroll
                for (int j = 0; j < 4; j++)
                    s[i][j] = fmaf(qa[i], ka[j], s[i][j]);
        }

        // mask (N,1,L) broadcast over query rows
        int mk[4];
#pragma unroll
        for (int j = 0; j < 4; j++) mk[j] = mrow[kt + tx * 4 + j];
#pragma unroll
        for (int i = 0; i < 8; i++)
#pragma unroll
            for (int j = 0; j < 4; j++)
                if (mk[j] == 0) s[i][j] = -1e9f;

        // Online softmax update (16-lane row groups; shfl_xor stays in group)
#pragma unroll
        for (int i = 0; i < 8; i++) {
            float mx = fmaxf(fmaxf(s[i][0], s[i][1]), fmaxf(s[i][2], s[i][3]));
#pragma unroll
            for (int off = 1; off < 16; off <<= 1)
                mx = fmaxf(mx, __shfl_xor_sync(0xffffffffu, mx, off));
            const float mn = fmaxf(m_i[i], mx);
            const float corr = __expf(m_i[i] - mn);
            float rs = 0.0f;
#pragma unroll
            for (int j = 0; j < 4; j++) {
                s[i][j] = __expf(s[i][j] - mn);
                rs += s[i][j];
            }
#pragma unroll
            for (int off = 1; off < 16; off <<= 1)
                rs += __shfl_xor_sync(0xffffffffu, rs, off);
            l_i[i] = l_i[i] * corr + rs;
            m_i[i] = mn;
#pragma unroll
            for (int j = 0; j < 4; j++) O[i][j] *= corr;
        }

        // Write P transposed: Pt[k][r]
#pragma unroll
        for (int j = 0; j < 4; j++) {
            const int c = tx * 4 + j;
#pragma unroll
            for (int i = 0; i < 8; i++)
                Pt[c * 128 + ty * 8 + i] = s[i][j];
        }
        __syncthreads();

        // O += P @ V
#pragma unroll 4
        for (int kk = 0; kk < 64; kk++) {
            float4 pv0 = *(const float4*)&Pt[kk * 128 + ty * 8];
            float4 pv1 = *(const float4*)&Pt[kk * 128 + ty * 8 + 4];
            float4 vv  = *(const float4*)&Vs[kk * 64 + tx * 4];
            float pa[8] = {pv0.x, pv0.y, pv0.z, pv0.w, pv1.x, pv1.y, pv1.z, pv1.w};
            float va[4] = {vv.x, vv.y, vv.z, vv.w};
#pragma unroll
            for (int i = 0; i < 8; i++)
#pragma unroll
                for (int j = 0; j < 4; j++)
                    O[i][j] = fmaf(pa[i], va[j], O[i][j]);
        }
    }

    // Normalize and write concatenated-head layout [b*l, h*64+d]
#pragma unroll
    for (int i = 0; i < 8; i++) {
        const float inv = 1.0f / l_i[i];
        const int row = q0 + ty * 8 + i;
#pragma unroll
        for (int j = 0; j < 4; j++)
            out[((size_t)b * LSEQ + row) * DMOD + h * DKH + tx * 4 + j] = O[i][j] * inv;
    }
}

// ----------------------------------------------------------------------------
extern "C" void kernel_launch(void* const* d_in, const int* in_sizes, int n_in,
                              void* d_out, int out_size)
{
    const float* query = (const float*)d_in[0];
    const float* key   = (const float*)d_in[1];
    const float* value = (const float*)d_in[2];
    const int*   mask  = (const int*)  d_in[3];
    const float* Wq = (const float*)d_in[4];
    const float* bq = (const float*)d_in[5];
    const float* Wk = (const float*)d_in[6];
    const float* bk = (const float*)d_in[7];
    const float* Wv = (const float*)d_in[8];
    const float* bv = (const float*)d_in[9];
    const float* Wo = (const float*)d_in[10];
    const float* bo = (const float*)d_in[11];
    float* out = (float*)d_out;

    float *qb, *kb, *vb, *ab;
    cudaGetSymbolAddress((void**)&qb, g_q);
    cudaGetSymbolAddress((void**)&kb, g_k);
    cudaGetSymbolAddress((void**)&vb, g_v);
    cudaGetSymbolAddress((void**)&ab, g_attn);

    const int attn_smem = ATTN_SMEM_FLOATS * (int)sizeof(float);  // 96 KB
    cudaFuncSetAttribute(attn512, cudaFuncAttributeMaxDynamicSharedMemorySize, attn_smem);

    dim3 blk(256);
    dim3 ggrid(DMOD / 128, MTOT / 128);   // (4, 64)

    gemm512<true><<<ggrid, blk>>>(query, Wq, bq, qb);
    gemm512<true><<<ggrid, blk>>>(key,   Wk, bk, kb);
    gemm512<true><<<ggrid, blk>>>(value, Wv, bv, vb);

    attn512<<<dim3(LSEQ / 128, NB * HH), blk, attn_smem>>>(qb, kb, vb, mask, ab);

    gemm512<false><<<ggrid, blk>>>(ab, Wo, bo, out);
}